// round 1
// baseline (speedup 1.0000x reference)
#include <cuda_runtime.h>
#include <cstddef>

#define B 8
#define L 2048
#define H 8
#define D 64
#define BH (B*H)          // 64
#define SK 40
#define U  40
#define HD (H*D)          // 512
#define SCALE 0.125f      // 1/sqrt(64)
#define KSPLIT 8
#define KT 256

// ---- scratch (device globals; no allocation allowed) ----
__device__ float g_M[BH * L];                 // 512 KB
__device__ int   g_top[BH * U];               // selected query indices
__device__ float g_vmean[BH * D];             // V mean per (b,h)
__device__ float g_scores[(size_t)BH * U * L];// 21 MB: raw scores -> softmax'd attn
__device__ float g_pv[BH * KSPLIT * U * D];   // 5.2 MB partial PV

// ------------------------------------------------------------------
// K1: M[b,h,q] = max_s(dot) - mean_s(dot) over 40 sampled keys.
// 2 queries per warp; 16 lanes per query, float4 per lane, 4-step reduce.
// ------------------------------------------------------------------
__global__ void k_probe_M(const float* __restrict__ Q, const float* __restrict__ Kp,
                          const int* __restrict__ IS) {
    int wg   = blockIdx.x * (blockDim.x >> 5) + (threadIdx.x >> 5);
    int lane = threadIdx.x & 31;
    int qh   = lane >> 4;        // which query in the pair
    int li   = lane & 15;        // lane within query group
    int qi   = wg * 2 + qh;      // 0 .. BH*L-1
    int bh   = qi >> 11;
    int q    = qi & (L - 1);
    int b = bh >> 3, h = bh & 7;

    float4 ql = *(const float4*)(Q + (size_t)(b * L + q) * HD + h * D + 4 * li);
    const int* isrow = IS + q * SK;
    float mx = -3.4e38f, sm = 0.f;
    #pragma unroll 4
    for (int s = 0; s < SK; ++s) {
        int idx = __ldg(isrow + s);
        float4 kv = *(const float4*)(Kp + (size_t)(b * L + idx) * HD + h * D + 4 * li);
        float p = ql.x * kv.x + ql.y * kv.y + ql.z * kv.z + ql.w * kv.w;
        p += __shfl_xor_sync(0xffffffffu, p, 8);
        p += __shfl_xor_sync(0xffffffffu, p, 4);
        p += __shfl_xor_sync(0xffffffffu, p, 2);
        p += __shfl_xor_sync(0xffffffffu, p, 1);
        mx = fmaxf(mx, p);
        sm += p;
    }
    if (li == 0) g_M[bh * L + q] = mx - sm * (1.f / SK);
}

// ------------------------------------------------------------------
// K2: V mean over L per (b,h,d)
// ------------------------------------------------------------------
__global__ void k_vmean(const float* __restrict__ V) {
    __shared__ float smem[4 * 64];
    int bh = blockIdx.x; int b = bh >> 3, h = bh & 7;
    int d = threadIdx.x & 63, p = threadIdx.x >> 6;
    float s = 0.f;
    for (int l = p; l < L; l += 4)
        s += V[(size_t)(b * L + l) * HD + h * D + d];
    smem[p * 64 + d] = s;
    __syncthreads();
    if (threadIdx.x < 64) {
        float t = smem[threadIdx.x] + smem[64 + threadIdx.x]
                + smem[128 + threadIdx.x] + smem[192 + threadIdx.x];
        g_vmean[bh * 64 + threadIdx.x] = t * (1.f / L);
    }
}

// ------------------------------------------------------------------
// K3: exact top-40 of M per (b,h). Keys pack (monotone f32, ~index) so
// max-selection matches jax top_k ordering (ties -> lower index).
// ------------------------------------------------------------------
__global__ void k_topk() {
    __shared__ unsigned long long key[L];
    __shared__ unsigned long long wred[8];
    int bh = blockIdx.x;
    int t = threadIdx.x, lane = t & 31, w = t >> 5;
    for (int i = t; i < L; i += 256) {
        unsigned int bits = __float_as_uint(g_M[bh * L + i]);
        bits = (bits & 0x80000000u) ? ~bits : (bits | 0x80000000u);
        key[i] = ((unsigned long long)bits << 32) | (unsigned int)(L - 1 - i);
    }
    __syncthreads();
    for (int it = 0; it < U; ++it) {
        unsigned long long best = 0ull;
        for (int i = t; i < L; i += 256) {
            unsigned long long v = key[i];
            if (v > best) best = v;
        }
        #pragma unroll
        for (int o = 16; o; o >>= 1) {
            unsigned long long other = __shfl_xor_sync(0xffffffffu, best, o);
            if (other > best) best = other;
        }
        if (lane == 0) wred[w] = best;
        __syncthreads();
        if (t == 0) {
            unsigned long long bb = wred[0];
            #pragma unroll
            for (int i = 1; i < 8; ++i) if (wred[i] > bb) bb = wred[i];
            int pos = (L - 1) - (int)(bb & 0xffffffffu);
            g_top[bh * U + it] = pos;
            key[pos] = 0ull;    // below any real key
        }
        __syncthreads();
    }
}

// ------------------------------------------------------------------
// K4: fill whole output with broadcast V-mean (selected rows overwritten later)
// ------------------------------------------------------------------
__global__ void k_fill(float* __restrict__ out) {
    int i4 = blockIdx.x * blockDim.x + threadIdx.x;   // exactly B*L*HD/4 threads
    int linear = i4 * 4;
    int d = linear & 63;
    int h = (linear >> 6) & 7;
    int b = linear >> 20;                // L*HD = 2^20 per batch
    float4 v = *(const float4*)&g_vmean[(b * 8 + h) * 64 + d];
    *(float4*)(out + linear) = v;
}

// ------------------------------------------------------------------
// K5: scores[bh, u, k] = (Q_sel . K) * scale.  Block = (ktile, bh).
// K tile in smem pitch-65 (conflict-free), 5u x 4k accumulators/thread.
// ------------------------------------------------------------------
__global__ void k_scores(const float* __restrict__ Q, const float* __restrict__ Kp) {
    extern __shared__ float smem[];
    float* Ksm = smem;               // KT * 65
    float* Qsm = smem + KT * 65;     // U * 64
    int bh = blockIdx.y, kt = blockIdx.x;
    int b = bh >> 3, h = bh & 7;
    int k0 = kt * KT;
    int t = threadIdx.x;             // 512

    for (int i4 = t; i4 < U * 16; i4 += 512) {
        int u = i4 >> 4, d4 = (i4 & 15) * 4;
        int qidx = g_top[bh * U + u];
        float4 v = *(const float4*)&Q[(size_t)(b * L + qidx) * HD + h * D + d4];
        *(float4*)&Qsm[u * 64 + d4] = v;
    }
    for (int i4 = t; i4 < KT * 16; i4 += 512) {
        int k = i4 >> 4, d4 = (i4 & 15) * 4;
        float4 v = *(const float4*)&Kp[(size_t)(b * L + k0 + k) * HD + h * D + d4];
        Ksm[k * 65 + d4 + 0] = v.x;
        Ksm[k * 65 + d4 + 1] = v.y;
        Ksm[k * 65 + d4 + 2] = v.z;
        Ksm[k * 65 + d4 + 3] = v.w;
    }
    __syncthreads();

    int kg = t & 63, ug = t >> 6;
    int u0 = ug * 5;
    float acc[5][4];
    #pragma unroll
    for (int i = 0; i < 5; ++i)
        #pragma unroll
        for (int j = 0; j < 4; ++j) acc[i][j] = 0.f;

    #pragma unroll 4
    for (int d = 0; d < 64; ++d) {
        float kv[4], qv[5];
        #pragma unroll
        for (int j = 0; j < 4; ++j) kv[j] = Ksm[(kg + 64 * j) * 65 + d];
        #pragma unroll
        for (int i = 0; i < 5; ++i) qv[i] = Qsm[(u0 + i) * 64 + d];
        #pragma unroll
        for (int i = 0; i < 5; ++i)
            #pragma unroll
            for (int j = 0; j < 4; ++j)
                acc[i][j] = fmaf(qv[i], kv[j], acc[i][j]);
    }
    #pragma unroll
    for (int i = 0; i < 5; ++i)
        #pragma unroll
        for (int j = 0; j < 4; ++j)
            g_scores[(size_t)(bh * U + u0 + i) * L + k0 + kg + 64 * j] = acc[i][j] * SCALE;
}

// ------------------------------------------------------------------
// K6: row softmax over 2048, in place, values held in registers
// ------------------------------------------------------------------
__global__ void k_softmax() {
    __shared__ float red[8];
    size_t row = blockIdx.x;
    float* p = g_scores + row * L;
    int t = threadIdx.x, lane = t & 31, w = t >> 5;
    float4 v0 = *(float4*)&p[4 * t];
    float4 v1 = *(float4*)&p[4 * (t + 256)];
    float m = fmaxf(fmaxf(fmaxf(v0.x, v0.y), fmaxf(v0.z, v0.w)),
                    fmaxf(fmaxf(v1.x, v1.y), fmaxf(v1.z, v1.w)));
    #pragma unroll
    for (int o = 16; o; o >>= 1) m = fmaxf(m, __shfl_xor_sync(0xffffffffu, m, o));
    if (lane == 0) red[w] = m;
    __syncthreads();
    m = red[0];
    #pragma unroll
    for (int i = 1; i < 8; ++i) m = fmaxf(m, red[i]);
    __syncthreads();

    v0.x = __expf(v0.x - m); v0.y = __expf(v0.y - m);
    v0.z = __expf(v0.z - m); v0.w = __expf(v0.w - m);
    v1.x = __expf(v1.x - m); v1.y = __expf(v1.y - m);
    v1.z = __expf(v1.z - m); v1.w = __expf(v1.w - m);
    float s = v0.x + v0.y + v0.z + v0.w + v1.x + v1.y + v1.z + v1.w;
    #pragma unroll
    for (int o = 16; o; o >>= 1) s += __shfl_xor_sync(0xffffffffu, s, o);
    if (lane == 0) red[w] = s;
    __syncthreads();
    s = red[0];
    #pragma unroll
    for (int i = 1; i < 8; ++i) s += red[i];
    float inv = 1.f / s;
    v0.x *= inv; v0.y *= inv; v0.z *= inv; v0.w *= inv;
    v1.x *= inv; v1.y *= inv; v1.z *= inv; v1.w *= inv;
    *(float4*)&p[4 * t] = v0;
    *(float4*)&p[4 * (t + 256)] = v1;
}

// ------------------------------------------------------------------
// K7: partial PV: out_part[bh,ks,u,d] = sum_{k in tile} attn[u,k] * V[k,d]
// Block = (ksplit, bh), 128 threads, 5u x 4d accumulators/thread.
// ------------------------------------------------------------------
__global__ void k_pv(const float* __restrict__ V) {
    extern __shared__ float smem[];
    float* Vsm = smem;               // KT * 64
    float* Asm = smem + KT * 64;     // U * 260
    int bh = blockIdx.y, ks = blockIdx.x;
    int b = bh >> 3, h = bh & 7;
    int k0 = ks * KT;
    int t = threadIdx.x;             // 128

    for (int i4 = t; i4 < U * (KT / 4); i4 += 128) {
        int u = i4 >> 6, k4 = (i4 & 63) * 4;
        float4 a = *(const float4*)&g_scores[(size_t)(bh * U + u) * L + k0 + k4];
        *(float4*)&Asm[u * 260 + k4] = a;
    }
    for (int i4 = t; i4 < KT * 16; i4 += 128) {
        int k = i4 >> 4, d4 = (i4 & 15) * 4;
        *(float4*)&Vsm[k * 64 + d4] =
            *(const float4*)&V[(size_t)(b * L + k0 + k) * HD + h * D + d4];
    }
    __syncthreads();

    int ug = t & 7, dg = t >> 3;
    int u0 = ug * 5, d0 = dg * 4;
    float4 acc[5];
    #pragma unroll
    for (int i = 0; i < 5; ++i) acc[i] = make_float4(0.f, 0.f, 0.f, 0.f);

    #pragma unroll 2
    for (int k = 0; k < KT; ++k) {
        float4 v = *(float4*)&Vsm[k * 64 + d0];
        #pragma unroll
        for (int i = 0; i < 5; ++i) {
            float a = Asm[(u0 + i) * 260 + k];
            acc[i].x = fmaf(a, v.x, acc[i].x);
            acc[i].y = fmaf(a, v.y, acc[i].y);
            acc[i].z = fmaf(a, v.z, acc[i].z);
            acc[i].w = fmaf(a, v.w, acc[i].w);
        }
    }
    #pragma unroll
    for (int i = 0; i < 5; ++i)
        *(float4*)&g_pv[(size_t)((bh * KSPLIT + ks) * U + u0 + i) * D + d0] = acc[i];
}

// ------------------------------------------------------------------
// K8: reduce KSPLIT partials and scatter into output at selected queries
// ------------------------------------------------------------------
__global__ void k_final(float* __restrict__ out) {
    int i4 = blockIdx.x * blockDim.x + threadIdx.x;  // BH*U*16 items
    if (i4 >= BH * U * 16) return;
    int d4 = (i4 & 15) * 4;
    int u  = (i4 >> 4) % U;
    int bh = i4 / (U * 16);
    float4 s = make_float4(0.f, 0.f, 0.f, 0.f);
    #pragma unroll
    for (int ks = 0; ks < KSPLIT; ++ks) {
        float4 p = *(const float4*)&g_pv[(size_t)((bh * KSPLIT + ks) * U + u) * D + d4];
        s.x += p.x; s.y += p.y; s.z += p.z; s.w += p.w;
    }
    int q = g_top[bh * U + u];
    int b = bh >> 3, h = bh & 7;
    *(float4*)&out[(size_t)(b * L + q) * HD + h * D + d4] = s;
}

// ------------------------------------------------------------------
extern "C" void kernel_launch(void* const* d_in, const int* in_sizes, int n_in,
                              void* d_out, int out_size) {
    const float* Q = (const float*)d_in[0];
    const float* K = (const float*)d_in[1];
    const float* V = (const float*)d_in[2];
    const int*  IS = (const int*)d_in[3];
    float* out = (float*)d_out;

    const int smem_scores = (KT * 65 + U * 64) * 4;        // 76800 B
    const int smem_pv     = (KT * 64 + U * 260) * 4;       // 107136 B
    cudaFuncSetAttribute(k_scores, cudaFuncAttributeMaxDynamicSharedMemorySize, smem_scores);
    cudaFuncSetAttribute(k_pv,     cudaFuncAttributeMaxDynamicSharedMemorySize, smem_pv);

    k_probe_M<<<(BH * L / 2) / 8, 256>>>(Q, K, IS);        // 8192 blocks
    k_vmean  <<<BH, 256>>>(V);
    k_topk   <<<BH, 256>>>();
    k_scores <<<dim3(L / KT, BH), 512, smem_scores>>>(Q, K);
    k_softmax<<<BH * U, 256>>>();
    k_fill   <<<(B * L * HD / 4) / 256, 256>>>(out);
    k_pv     <<<dim3(L / KT, BH), 128, smem_pv>>>(V);
    k_final  <<<(BH * U * 16 + 255) / 256, 256>>>(out);
}